// round 3
// baseline (speedup 1.0000x reference)
#include <cuda_runtime.h>
#include <cuda_bf16.h>
#include <cstdint>
#include <cstddef>

#define BB 16
#define IC 8
#define OC 8
#define NV 3
#define HH 256
#define WW 256
#define M1 16
#define M2 16
#define TD 256

// -------------------- static scratch (no runtime allocation) --------------------
// g_Y : fwd DFT over w     [b,i,v,h,kw]        98304 rows x 16 modes, complex
// g_X : fwd modes          [b,i,v,slot,kw]     slot 0..15 -> kh=slot, 16..31 -> kh=240+(slot-16)
// g_TW: time-contracted w  [arr][b][row]       arr: 0=w1r,1=w1i,2=w2r,3=w2i ; row=(((i*8+o)*3+v)*16+y)*16+kw
// g_G : mixed modes        [b,o,v,slot,kw]
// g_Z : inv DFT over h     [b,o,v,h,kw]
__device__ __align__(16) float2 g_Y[BB*IC*NV*HH*16];
__device__ __align__(16) float2 g_X[BB*IC*NV*32*16];
__device__ __align__(16) float  g_TW[4*BB*(IC*OC*NV*M1*M2)];
__device__ __align__(16) float2 g_G[BB*OC*NV*32*16];
__device__ __align__(16) float2 g_Z[BB*OC*NV*HH*16];

// ---------------------------------------------------------------------------
// k1: forward DFT over w, modes kw=0..15, for every (b,i,v,h) row.
// Parity split: for even kw use x[w]+x[w+128], odd kw use x[w]-x[w+128], w<128.
// Twiddle e^{-2pi i kw w/256} generated by incremental complex rotation.
// Block: 128 threads = 16 modes x 8 row-groups; 32 rows per block. Grid: 3072.
// ---------------------------------------------------------------------------
__global__ __launch_bounds__(128) void k1_fwd_w(const float* __restrict__ x) {
    __shared__ float sx[32][256];
    const int tid = threadIdx.x;

    const float4* xg = (const float4*)(x + (size_t)blockIdx.x * (32 * 256));
    float4* sx4 = (float4*)sx;
#pragma unroll
    for (int it = 0; it < 16; it++)
        sx4[it * 128 + tid] = xg[it * 128 + tid];
    __syncthreads();

    // in-place parity: rows keep sum in cols [0,128), diff in [128,256)
#pragma unroll
    for (int p = tid; p < 4096; p += 128) {
        int r = p >> 7, w = p & 127;
        float a = sx[r][w], b = sx[r][w + 128];
        sx[r][w]       = a + b;
        sx[r][w + 128] = a - b;
    }
    __syncthreads();

    const int k  = tid & 15;
    const int rg = tid >> 4;           // 0..7
    const int base = (k & 1) << 7;     // odd modes read diff half

    float sn, cs;
    sincospif((float)k * (1.0f / 128.0f), &sn, &cs);
    const float stc = cs, sts = -sn;   // step = e^{-2pi i k/256}
    float pc = 1.0f, ps = 0.0f;

    float ar0 = 0, ai0 = 0, ar1 = 0, ai1 = 0, ar2 = 0, ai2 = 0, ar3 = 0, ai3 = 0;
#pragma unroll 4
    for (int w = 0; w < 128; w++) {
        float u0 = sx[rg     ][base + w];
        float u1 = sx[rg +  8][base + w];
        float u2 = sx[rg + 16][base + w];
        float u3 = sx[rg + 24][base + w];
        ar0 += u0 * pc; ai0 += u0 * ps;
        ar1 += u1 * pc; ai1 += u1 * ps;
        ar2 += u2 * pc; ai2 += u2 * ps;
        ar3 += u3 * pc; ai3 += u3 * ps;
        float npc = pc * stc - ps * sts;
        float nps = pc * sts + ps * stc;
        pc = npc; ps = nps;
    }

    size_t rowbase = (size_t)blockIdx.x * 32;
    g_Y[(rowbase + rg     ) * 16 + k] = make_float2(ar0, ai0);
    g_Y[(rowbase + rg +  8) * 16 + k] = make_float2(ar1, ai1);
    g_Y[(rowbase + rg + 16) * 16 + k] = make_float2(ar2, ai2);
    g_Y[(rowbase + rg + 24) * 16 + k] = make_float2(ar3, ai3);
}

// ---------------------------------------------------------------------------
// k2: forward DFT over h for kh in {0..15} U {240..255}. One block per (b,i,v).
// Thread (kw = tid&15, s = tid>>4) produces kh=s and kh=240+s (same parity).
// Grid: 384, 256 threads.
// ---------------------------------------------------------------------------
__global__ __launch_bounds__(256) void k2_fwd_h() {
    __shared__ float2 sy[4096];   // [h][kw]
    const int tid = threadIdx.x;

    const float4* yg = (const float4*)(g_Y + (size_t)blockIdx.x * 4096);
    float4* sy4 = (float4*)sy;
#pragma unroll
    for (int it = 0; it < 8; it++)
        sy4[it * 256 + tid] = yg[it * 256 + tid];
    __syncthreads();

#pragma unroll
    for (int p = tid; p < 2048; p += 256) {
        int h = p >> 4, kw = p & 15;
        float2 a = sy[h * 16 + kw], b = sy[(h + 128) * 16 + kw];
        sy[h * 16 + kw]         = make_float2(a.x + b.x, a.y + b.y);
        sy[(h + 128) * 16 + kw] = make_float2(a.x - b.x, a.y - b.y);
    }
    __syncthreads();

    const int kw = tid & 15;
    const int s  = tid >> 4;             // 0..15
    const int hbase = (s & 1) << 7;      // parity of both kh=s and kh=240+s is parity(s)

    float s1, c1, s2, c2;
    sincospif((float)s * (1.0f / 128.0f), &s1, &c1);
    sincospif((float)(s - 16) * (1.0f / 128.0f), &s2, &c2);  // kh=240+s == s-16 (mod 256)
    const float st1c = c1, st1s = -s1;
    const float st2c = c2, st2s = -s2;
    float p1c = 1, p1s = 0, p2c = 1, p2s = 0;
    float a1r = 0, a1i = 0, a2r = 0, a2i = 0;

#pragma unroll 4
    for (int h = 0; h < 128; h++) {
        float2 u = sy[(hbase + h) * 16 + kw];
        a1r += u.x * p1c - u.y * p1s;
        a1i += u.x * p1s + u.y * p1c;
        a2r += u.x * p2c - u.y * p2s;
        a2i += u.x * p2s + u.y * p2c;
        float n;
        n = p1c * st1c - p1s * st1s; p1s = p1c * st1s + p1s * st1c; p1c = n;
        n = p2c * st2c - p2s * st2s; p2s = p2c * st2s + p2s * st2c; p2c = n;
    }

    size_t ob = (size_t)blockIdx.x * 512;
    g_X[ob + s * 16 + kw]        = make_float2(a1r, a1i);
    g_X[ob + (16 + s) * 16 + kw] = make_float2(a2r, a2i);
}

// ---------------------------------------------------------------------------
// k3a: time contraction TW[arr][b][row] = sum_t t[b,t] * W[row, t]
// 4 weight arrays x 49152 rows x TD=256. GEMM with K=256, N=16 (batches).
// Block: 128 threads, 4 rows/thread -> 512 rows/block. Grid: (96, 4).
// ---------------------------------------------------------------------------
__global__ __launch_bounds__(128) void k3a_time(const float* __restrict__ t,
                                                const float* __restrict__ wa,
                                                const float* __restrict__ wb,
                                                const float* __restrict__ wc,
                                                const float* __restrict__ wd) {
    __shared__ float ts[256][16];   // ts[k][b]
    const int tid = threadIdx.x;
#pragma unroll
    for (int j = tid; j < 4096; j += 128) {
        int b = j & 15, k = j >> 4;
        ts[k][b] = t[b * 256 + k];
    }
    __syncthreads();

    const float* W = (blockIdx.y == 0) ? wa : (blockIdx.y == 1) ? wb
                   : (blockIdx.y == 2) ? wc : wd;
    float* out = g_TW + (size_t)blockIdx.y * (16 * 49152);

    const int row0 = blockIdx.x * 512 + tid * 4;
    float acc[4][16];
#pragma unroll
    for (int r = 0; r < 4; r++)
#pragma unroll
        for (int b = 0; b < 16; b++) acc[r][b] = 0.0f;

    const float4* Wp = (const float4*)(W + (size_t)row0 * 256);  // row r at float4-offset r*64

    for (int k4 = 0; k4 < 64; k4++) {
        float4 wv0 = Wp[k4];
        float4 wv1 = Wp[64 + k4];
        float4 wv2 = Wp[128 + k4];
        float4 wv3 = Wp[192 + k4];
#pragma unroll
        for (int kk = 0; kk < 4; kk++) {
            const float4* trp = (const float4*)&ts[k4 * 4 + kk][0];
            float4 ta = trp[0], tb = trp[1], tc = trp[2], td = trp[3];
            float wf[4];
            wf[0] = (kk == 0) ? wv0.x : (kk == 1) ? wv0.y : (kk == 2) ? wv0.z : wv0.w;
            wf[1] = (kk == 0) ? wv1.x : (kk == 1) ? wv1.y : (kk == 2) ? wv1.z : wv1.w;
            wf[2] = (kk == 0) ? wv2.x : (kk == 1) ? wv2.y : (kk == 2) ? wv2.z : wv2.w;
            wf[3] = (kk == 0) ? wv3.x : (kk == 1) ? wv3.y : (kk == 2) ? wv3.z : wv3.w;
#pragma unroll
            for (int r = 0; r < 4; r++) {
                acc[r][0]  += wf[r] * ta.x; acc[r][1]  += wf[r] * ta.y;
                acc[r][2]  += wf[r] * ta.z; acc[r][3]  += wf[r] * ta.w;
                acc[r][4]  += wf[r] * tb.x; acc[r][5]  += wf[r] * tb.y;
                acc[r][6]  += wf[r] * tb.z; acc[r][7]  += wf[r] * tb.w;
                acc[r][8]  += wf[r] * tc.x; acc[r][9]  += wf[r] * tc.y;
                acc[r][10] += wf[r] * tc.z; acc[r][11] += wf[r] * tc.w;
                acc[r][12] += wf[r] * td.x; acc[r][13] += wf[r] * td.y;
                acc[r][14] += wf[r] * td.z; acc[r][15] += wf[r] * td.w;
            }
        }
    }

#pragma unroll
    for (int b = 0; b < 16; b++) {
        float4 v = make_float4(acc[0][b], acc[1][b], acc[2][b], acc[3][b]);
        *(float4*)&out[(size_t)b * 49152 + row0] = v;
    }
}

// ---------------------------------------------------------------------------
// k3b: spectral mixing  G[b,o,v,s,kw] = sum_i X[b,i,v,s,kw] * TW[b,i,o,v,y,kw]
// slot<16 -> w1 (arrays 0,1); slot>=16 -> w2 (arrays 2,3), y = s & 15.
// One thread per output element. Grid: 768 x 256.
// ---------------------------------------------------------------------------
__global__ __launch_bounds__(256) void k3b_mix() {
    const int gtid = blockIdx.x * 256 + threadIdx.x;   // < 196608
    const int kw = gtid & 15;
    int r = gtid >> 4;
    const int s = r & 31; r >>= 5;
    const int v = r % 3;  r /= 3;
    const int o = r & 7;
    const int b = r >> 3;

    const int arrbase = (s < 16) ? 0 : 2;
    const int y = s & 15;
    const float* TR = g_TW + (size_t)(arrbase * 16 + b) * 49152;
    const float* TI = g_TW + (size_t)((arrbase + 1) * 16 + b) * 49152;

    float gr = 0.0f, gi = 0.0f;
#pragma unroll
    for (int i = 0; i < 8; i++) {
        float2 xf = g_X[((size_t)((b * 8 + i) * 3 + v) * 32 + s) * 16 + kw];
        int row = (((i * 8 + o) * 3 + v) * 16 + y) * 16 + kw;
        float wr = TR[row], wi = TI[row];
        gr += xf.x * wr - xf.y * wi;
        gi += xf.x * wi + xf.y * wr;
    }
    g_G[gtid] = make_float2(gr, gi);
}

// ---------------------------------------------------------------------------
// k4: inverse DFT over h:  Z[b,o,v,h,kw] = sum_slot G[slot,kw] e^{+2pi i kh(slot) h/256}
// One block per (b,o,v), thread = h. Grid: 384 x 256. (1/256 scale folded into k5.)
// ---------------------------------------------------------------------------
__global__ __launch_bounds__(256) void k4_inv_h() {
    __shared__ float2 Gs[512];
    const int tid = threadIdx.x;
    ((float4*)Gs)[tid] = ((const float4*)(g_G + (size_t)blockIdx.x * 512))[tid];
    __syncthreads();

    const int h = tid;
    float zr[16], zi[16];
#pragma unroll
    for (int q = 0; q < 16; q++) { zr[q] = 0.0f; zi[q] = 0.0f; }

#pragma unroll 1
    for (int sl = 0; sl < 32; sl++) {
        int kh = (sl < 16) ? sl : (224 + sl);   // 240 + (sl-16)
        float sn, cs;
        sincospif((float)(kh * h) * (1.0f / 128.0f), &sn, &cs);  // e^{+i theta}
#pragma unroll
        for (int q = 0; q < 16; q++) {
            float2 g = Gs[sl * 16 + q];
            zr[q] += g.x * cs - g.y * sn;
            zi[q] += g.x * sn + g.y * cs;
        }
    }

    float4* zp = (float4*)(g_Z + (size_t)blockIdx.x * 4096 + h * 16);
#pragma unroll
    for (int q = 0; q < 8; q++)
        zp[q] = make_float4(zr[2 * q], zi[2 * q], zr[2 * q + 1], zi[2 * q + 1]);
}

// ---------------------------------------------------------------------------
// k5: inverse real DFT over w:
//   out[h,w] = (1/65536) [ Re Z[h,0] + 2 * sum_{kw=1..15} Re( Z[h,kw] e^{+2pi i kw w/256} ) ]
// Parity split over w: A (even kw) + B (odd kw); out[w]=A+B, out[w+128]=A-B.
// Tables in smem (2048 entries each -> 8 fill iters with 256 threads).
// Block: 32 rows, 256 threads (r = tid>>3, wb = tid&7, 16 w each). Grid: 3072.
// ---------------------------------------------------------------------------
__global__ __launch_bounds__(256) void k5_inv_w(float* __restrict__ out) {
    __shared__ float Ct[16 * 128];
    __shared__ float St[16 * 128];
    __shared__ float2 Zs[512];
    const int tid = threadIdx.x;

#pragma unroll
    for (int j = 0; j < 8; j++) {               // FIXED: 2048 entries / 256 threads
        int idx = tid + j * 256;
        int kwv = idx >> 7, w = idx & 127;
        float sn, cs;
        sincospif((float)(kwv * w) * (1.0f / 128.0f), &sn, &cs);
        float al = ((kwv == 0) ? 1.0f : 2.0f) * (1.0f / 65536.0f);
        Ct[idx] = cs * al;
        St[idx] = sn * al;
    }
    ((float4*)Zs)[tid] = ((const float4*)(g_Z + (size_t)blockIdx.x * 512))[tid];
    __syncthreads();

    const int r  = tid >> 3;   // 0..31 (row within block)
    const int wb = tid & 7;    // w chunk: w = wb*16 + u, u=0..15

    float A[16], B[16];
#pragma unroll
    for (int u = 0; u < 16; u++) { A[u] = 0.0f; B[u] = 0.0f; }

#pragma unroll
    for (int kwv = 0; kwv < 16; kwv++) {
        float2 z = Zs[r * 16 + kwv];
#pragma unroll
        for (int u4 = 0; u4 < 4; u4++) {
            float4 c4 = *(const float4*)&Ct[kwv * 128 + wb * 16 + u4 * 4];
            float4 s4 = *(const float4*)&St[kwv * 128 + wb * 16 + u4 * 4];
            if ((kwv & 1) == 0) {
                A[u4 * 4 + 0] += z.x * c4.x - z.y * s4.x;
                A[u4 * 4 + 1] += z.x * c4.y - z.y * s4.y;
                A[u4 * 4 + 2] += z.x * c4.z - z.y * s4.z;
                A[u4 * 4 + 3] += z.x * c4.w - z.y * s4.w;
            } else {
                B[u4 * 4 + 0] += z.x * c4.x - z.y * s4.x;
                B[u4 * 4 + 1] += z.x * c4.y - z.y * s4.y;
                B[u4 * 4 + 2] += z.x * c4.z - z.y * s4.z;
                B[u4 * 4 + 3] += z.x * c4.w - z.y * s4.w;
            }
        }
    }

    float* orow = out + (size_t)blockIdx.x * (32 * 256) + r * 256 + wb * 16;
#pragma unroll
    for (int u4 = 0; u4 < 4; u4++) {
        float4 lo = make_float4(A[u4 * 4 + 0] + B[u4 * 4 + 0],
                                A[u4 * 4 + 1] + B[u4 * 4 + 1],
                                A[u4 * 4 + 2] + B[u4 * 4 + 2],
                                A[u4 * 4 + 3] + B[u4 * 4 + 3]);
        float4 hi = make_float4(A[u4 * 4 + 0] - B[u4 * 4 + 0],
                                A[u4 * 4 + 1] - B[u4 * 4 + 1],
                                A[u4 * 4 + 2] - B[u4 * 4 + 2],
                                A[u4 * 4 + 3] - B[u4 * 4 + 3]);
        *(float4*)&orow[u4 * 4]       = lo;
        *(float4*)&orow[128 + u4 * 4] = hi;
    }
}

// ---------------------------------------------------------------------------
extern "C" void kernel_launch(void* const* d_in, const int* in_sizes, int n_in,
                              void* d_out, int out_size) {
    // Resolve t and x by element count (robust to metadata ordering);
    // remaining four (all 12,582,912 elems) keep positional order: w1r,w1i,w2r,w2i.
    const float* t = nullptr;
    const float* x = nullptr;
    const float* w[4] = {nullptr, nullptr, nullptr, nullptr};
    int wn = 0;
    for (int i = 0; i < n_in; i++) {
        if (in_sizes[i] == BB * TD)                      t = (const float*)d_in[i];
        else if (in_sizes[i] == BB * IC * NV * HH * WW)  x = (const float*)d_in[i];
        else if (wn < 4)                                 w[wn++] = (const float*)d_in[i];
    }
    float* out = (float*)d_out;

    k1_fwd_w<<<3072, 128>>>(x);
    k2_fwd_h<<<384, 256>>>();
    k3a_time<<<dim3(96, 4), 128>>>(t, w[0], w[1], w[2], w[3]);
    k3b_mix<<<768, 256>>>();
    k4_inv_h<<<384, 256>>>();
    k5_inv_w<<<3072, 256>>>(out);
}